// round 3
// baseline (speedup 1.0000x reference)
#include <cuda_runtime.h>
#include <cstddef>

#define Nn 1024
#define BATCH 4096
#define NL 8
#define NB 128

// ---------------- device scratch (no allocations allowed) ----------------
__device__ float g_A[Nn * Nn];
__device__ float g_Linv[Nn * Nn];
__device__ float g_Dinv[8 * NB * NB];
__device__ float g_tmp[Nn * Nn];
__device__ float g_W[Nn * Nn];
__device__ float g_T[Nn * Nn];
__device__ float g_gamma[Nn * Nn];
__device__ float g_sigma[Nn * Nn];
__device__ float g_aw[Nn * Nn];
__device__ float g_cur[BATCH * Nn];
__device__ float g_cur2[BATCH * Nn];

// ---------------- potrf (128x128 diag block) + diag-block inverse ----------------
// One thread block, 256 threads. Factors lower Cholesky of the k-th diagonal
// 128-block of A (in place, zeros written to upper), and writes Dinv = inv(L_kk)
// (lower, zero upper). Fused right-looking factor + forward substitution.
extern __shared__ float s_potrf[];
__global__ void potrf_diag_kernel(float* A, int lda, int k, float* Dinv) {
    float(*sL)[NB + 1] = (float(*)[NB + 1]) s_potrf;
    float(*sX)[NB + 1] = (float(*)[NB + 1])(s_potrf + NB * (NB + 1));
    const int tid = threadIdx.x;
    float* Ab = A + (size_t)k * NB * lda + (size_t)k * NB;
    for (int idx = tid; idx < NB * NB; idx += 256) {
        int r = idx >> 7, c = idx & (NB - 1);
        sL[r][c] = Ab[(size_t)r * lda + c];
        sX[r][c] = (r == c) ? 1.0f : 0.0f;
    }
    __syncthreads();
    const int tx = tid & 7, ty = tid >> 3;  // 8 x 32
    for (int j = 0; j < NB; ++j) {
        if (tid == 0) sL[j][j] = sqrtf(sL[j][j]);
        __syncthreads();
        float invd = 1.0f / sL[j][j];
        for (int i = j + 1 + tid; i < NB; i += 256) sL[i][j] *= invd;
        for (int c = tid; c <= j; c += 256) sX[j][c] *= invd;
        __syncthreads();
        for (int i = j + 1 + ty; i < NB; i += 32) {
            float lij = sL[i][j];
            for (int c = j + 1 + tx; c <= i; c += 8) sL[i][c] -= lij * sL[c][j];
            for (int c = tx; c <= j; c += 8) sX[i][c] -= lij * sX[j][c];
        }
        __syncthreads();
    }
    for (int idx = tid; idx < NB * NB; idx += 256) {
        int r = idx >> 7, c = idx & (NB - 1);
        Ab[(size_t)r * lda + c] = (c <= r) ? sL[r][c] : 0.0f;
        Dinv[idx] = sX[r][c];
    }
}

// ---------------- general 64x64x16 SGEMM, templated transposes, z-batched ----------------
// C = alpha * op(A) * op(B) + beta * C (+ diagAdd on the global diagonal)
// All dims assumed multiples of 64 (M, N) and 16 (K) — true for every call site.
template <int TA, int TB>
__global__ void gemm64_kernel(const float* __restrict__ A, int lda, long long strA,
                              const float* __restrict__ B, int ldb, long long strB,
                              float* __restrict__ C, int ldc, long long strC, int K,
                              float alpha, float beta, float diagAdd, int lowerOnly) {
    const int bi = blockIdx.y, bj = blockIdx.x;
    if (lowerOnly && bj > bi) return;
    A += (long long)blockIdx.z * strA;
    B += (long long)blockIdx.z * strB;
    C += (long long)blockIdx.z * strC;
    __shared__ float As[16][68];
    __shared__ float Bs[16][68];
    const int tid = threadIdx.x;            // 128 threads
    const int tx = tid & 7, ty = tid >> 3;  // 8 x 16
    const int row0 = bi * 64, col0 = bj * 64;
    float acc[4][8];
#pragma unroll
    for (int i = 0; i < 4; ++i)
#pragma unroll
        for (int j = 0; j < 8; ++j) acc[i][j] = 0.0f;

    for (int k0 = 0; k0 < K; k0 += 16) {
        if (TA == 0) {
#pragma unroll
            for (int r = 0; r < 2; ++r) {
                int idx = tid + r * 128;
                int m = idx >> 2, kq = (idx & 3) * 4;
                float4 v = *(const float4*)(A + (long long)(row0 + m) * lda + k0 + kq);
                As[kq + 0][m] = v.x; As[kq + 1][m] = v.y;
                As[kq + 2][m] = v.z; As[kq + 3][m] = v.w;
            }
        } else {
#pragma unroll
            for (int r = 0; r < 2; ++r) {
                int idx = tid + r * 128;
                int kk = idx >> 4, mq = (idx & 15) * 4;
                float4 v = *(const float4*)(A + (long long)(k0 + kk) * lda + row0 + mq);
                *(float4*)&As[kk][mq] = v;
            }
        }
        if (TB == 0) {
#pragma unroll
            for (int r = 0; r < 2; ++r) {
                int idx = tid + r * 128;
                int kk = idx >> 4, nq = (idx & 15) * 4;
                float4 v = *(const float4*)(B + (long long)(k0 + kk) * ldb + col0 + nq);
                *(float4*)&Bs[kk][nq] = v;
            }
        } else {
#pragma unroll
            for (int r = 0; r < 2; ++r) {
                int idx = tid + r * 128;
                int n = idx >> 2, kq = (idx & 3) * 4;
                float4 v = *(const float4*)(B + (long long)(col0 + n) * ldb + k0 + kq);
                Bs[kq + 0][n] = v.x; Bs[kq + 1][n] = v.y;
                Bs[kq + 2][n] = v.z; Bs[kq + 3][n] = v.w;
            }
        }
        __syncthreads();
#pragma unroll
        for (int kk = 0; kk < 16; ++kk) {
            float a[4], b[8];
            *(float4*)a = *(const float4*)&As[kk][ty * 4];
            *(float4*)b = *(const float4*)&Bs[kk][tx * 8];
            *(float4*)(b + 4) = *(const float4*)&Bs[kk][tx * 8 + 4];
#pragma unroll
            for (int i = 0; i < 4; ++i)
#pragma unroll
                for (int j = 0; j < 8; ++j) acc[i][j] += a[i] * b[j];
        }
        __syncthreads();
    }
#pragma unroll
    for (int i = 0; i < 4; ++i) {
        int r = row0 + ty * 4 + i;
#pragma unroll
        for (int j = 0; j < 8; ++j) {
            int c = col0 + tx * 8 + j;
            float v = alpha * acc[i][j];
            if (beta != 0.0f) v += beta * C[(long long)r * ldc + c];
            if (r == c) v += diagAdd;
            C[(long long)r * ldc + c] = v;
        }
    }
}

// ---------------- batch SGEMM: C[M,1024] = A * W^T (+bias) (+beta*C), optional relu ----
// 128x128 tile, BK=8, 256 threads, 8x8 per thread.
__global__ void gemm_batch_kernel(const float* __restrict__ A, int lda,
                                  const float* __restrict__ Bw, int ldb,
                                  const float* __restrict__ bias, float* __restrict__ C,
                                  int ldc, int K, float beta, int relu) {
    __shared__ float As[8][132];
    __shared__ float Bs[8][132];
    const int tid = threadIdx.x;              // 256
    const int tx = tid & 15, ty = tid >> 4;   // 16 x 16
    const int row0 = blockIdx.y * 128, col0 = blockIdx.x * 128;
    float acc[8][8];
#pragma unroll
    for (int i = 0; i < 8; ++i)
#pragma unroll
        for (int j = 0; j < 8; ++j) acc[i][j] = 0.0f;

    for (int k0 = 0; k0 < K; k0 += 8) {
        {
            int m = tid >> 1, kq = (tid & 1) * 4;
            float4 v = *(const float4*)(A + (long long)(row0 + m) * lda + k0 + kq);
            As[kq + 0][m] = v.x; As[kq + 1][m] = v.y;
            As[kq + 2][m] = v.z; As[kq + 3][m] = v.w;
        }
        {
            int n = tid >> 1, kq = (tid & 1) * 4;
            float4 v = *(const float4*)(Bw + (long long)(col0 + n) * ldb + k0 + kq);
            Bs[kq + 0][n] = v.x; Bs[kq + 1][n] = v.y;
            Bs[kq + 2][n] = v.z; Bs[kq + 3][n] = v.w;
        }
        __syncthreads();
#pragma unroll
        for (int kk = 0; kk < 8; ++kk) {
            float a[8], b[8];
            *(float4*)a = *(const float4*)&As[kk][ty * 8];
            *(float4*)(a + 4) = *(const float4*)&As[kk][ty * 8 + 4];
            *(float4*)b = *(const float4*)&Bs[kk][tx * 8];
            *(float4*)(b + 4) = *(const float4*)&Bs[kk][tx * 8 + 4];
#pragma unroll
            for (int i = 0; i < 8; ++i)
#pragma unroll
                for (int j = 0; j < 8; ++j) acc[i][j] += a[i] * b[j];
        }
        __syncthreads();
    }
#pragma unroll
    for (int i = 0; i < 8; ++i) {
        int r = row0 + ty * 8 + i;
#pragma unroll
        for (int j = 0; j < 8; ++j) {
            int c = col0 + tx * 8 + j;
            float v = acc[i][j];
            if (bias) v += bias[c];
            if (beta != 0.0f) v += beta * C[(long long)r * ldc + c];
            if (relu) v = fmaxf(v, 0.0f);
            C[(long long)r * ldc + c] = v;
        }
    }
}

// ---------------- small utility kernels ----------------
__global__ void copy_panel_kernel(const float* __restrict__ src, float* __restrict__ dst,
                                  int rows, int ldd) {
    // src: rows x 128 contiguous (ld=128); dst: rows x 128 with leading dim ldd
    int total = rows * 32;  // float4 count
    for (int idx = blockIdx.x * blockDim.x + threadIdx.x; idx < total;
         idx += gridDim.x * blockDim.x) {
        int r = idx >> 5, q = idx & 31;
        *(float4*)(dst + (long long)r * ldd + q * 4) = *(const float4*)(src + r * 128 + q * 4);
    }
}

__global__ void set_identity_kernel(float* A) {
    for (int idx = blockIdx.x * blockDim.x + threadIdx.x; idx < Nn * Nn;
         idx += gridDim.x * blockDim.x) {
        int r = idx >> 10, c = idx & (Nn - 1);
        A[idx] = (r == c) ? 1.0f : 0.0f;
    }
}

__global__ void tril_copy_kernel(const float* __restrict__ A, float* __restrict__ S) {
    for (int idx = blockIdx.x * blockDim.x + threadIdx.x; idx < Nn * Nn;
         idx += gridDim.x * blockDim.x) {
        int r = idx >> 10, c = idx & (Nn - 1);
        S[idx] = (c <= r) ? A[idx] : 0.0f;
    }
}

__global__ void place_dinv_kernel(float* __restrict__ Linv, const float* __restrict__ Dinv) {
    for (int idx = blockIdx.x * blockDim.x + threadIdx.x; idx < 8 * NB * NB;
         idx += gridDim.x * blockDim.x) {
        int k = idx >> 14;
        int rem = idx & (NB * NB - 1);
        int r = rem >> 7, c = rem & (NB - 1);
        Linv[(long long)(k * NB + r) * Nn + k * NB + c] = Dinv[idx];
    }
}

// ---------------- host-side orchestration ----------------
static void launch_gemm64(int TA, int TB, const float* A, int lda, long long sA,
                          const float* B, int ldb, long long sB, float* C, int ldc,
                          long long sC, int M, int Ncols, int K, float alpha, float beta,
                          float diagAdd, int lowerOnly, int batch) {
    dim3 grid(Ncols / 64, M / 64, batch);
    if (TA == 0 && TB == 0)
        gemm64_kernel<0, 0><<<grid, 128>>>(A, lda, sA, B, ldb, sB, C, ldc, sC, K, alpha, beta, diagAdd, lowerOnly);
    else if (TA == 0 && TB == 1)
        gemm64_kernel<0, 1><<<grid, 128>>>(A, lda, sA, B, ldb, sB, C, ldc, sC, K, alpha, beta, diagAdd, lowerOnly);
    else if (TA == 1 && TB == 0)
        gemm64_kernel<1, 0><<<grid, 128>>>(A, lda, sA, B, ldb, sB, C, ldc, sC, K, alpha, beta, diagAdd, lowerOnly);
    else
        gemm64_kernel<1, 1><<<grid, 128>>>(A, lda, sA, B, ldb, sB, C, ldc, sC, K, alpha, beta, diagAdd, lowerOnly);
}

static const int POTRF_SMEM = 2 * NB * (NB + 1) * sizeof(float);

static void chol_inplace(float* A, float* Dinv, float* tmp) {
    for (int k = 0; k < Nn / NB; ++k) {
        potrf_diag_kernel<<<1, 256, POTRF_SMEM>>>(A, Nn, k, Dinv + (size_t)k * NB * NB);
        int rem = Nn - (k + 1) * NB;
        if (rem > 0) {
            float* panel = A + (size_t)(k + 1) * NB * Nn + (size_t)k * NB;
            // panel := panel * Dinv^T  (out of place, then copy back)
            launch_gemm64(0, 1, panel, Nn, 0, Dinv + (size_t)k * NB * NB, NB, 0, tmp, NB, 0,
                          rem, NB, NB, 1.0f, 0.0f, 0.0f, 0, 1);
            copy_panel_kernel<<<64, 256>>>(tmp, panel, rem, Nn);
            // trailing syrk (lower blocks only): At -= panel * panel^T
            float* At = A + (size_t)(k + 1) * NB * Nn + (size_t)(k + 1) * NB;
            launch_gemm64(0, 1, panel, Nn, 0, panel, Nn, 0, At, Nn, 0, rem, rem, NB, -1.0f,
                          1.0f, 0.0f, 1, 1);
        }
    }
}

static void build_linv(const float* A, float* Linv, const float* Dinv, float* tmp) {
    cudaMemsetAsync(Linv, 0, (size_t)Nn * Nn * sizeof(float));
    place_dinv_kernel<<<128, 256>>>(Linv, Dinv);
    for (int s = 128; s <= 512; s <<= 1) {
        int P = Nn / (2 * s);
        long long str = 2LL * s * (Nn + 1);
        // X1 = B_block * Ainv   (per pair)
        launch_gemm64(0, 0, A + (long long)s * Nn, Nn, str, Linv, Nn, str, tmp, s,
                      (long long)s * s, s, s, s, 1.0f, 0.0f, 0.0f, 0, P);
        // Linv_21 = -Cinv * X1
        launch_gemm64(0, 0, Linv + (long long)s * (Nn + 1), Nn, str, tmp, s,
                      (long long)s * s, Linv + (long long)s * Nn, Nn, str, s, s, s, -1.0f,
                      0.0f, 0.0f, 0, P);
    }
}

extern "C" void kernel_launch(void* const* d_in, const int* in_sizes, int n_in, void* d_out,
                              int out_size) {
    const float* x = (const float*)d_in[0];
    const float* Va = (const float*)d_in[1];
    const float* ba = (const float*)d_in[2];
    const float* Vin = (const float*)d_in[3];
    const float* bin = (const float*)d_in[4];
    const float* Vb = (const float*)d_in[5];
    float* out = (float*)d_out;

    float *dA, *dLinv, *dDinv, *dTmp, *dW, *dT, *dGamma, *dSigma, *dAw, *dCur, *dCur2;
    cudaGetSymbolAddress((void**)&dA, g_A);
    cudaGetSymbolAddress((void**)&dLinv, g_Linv);
    cudaGetSymbolAddress((void**)&dDinv, g_Dinv);
    cudaGetSymbolAddress((void**)&dTmp, g_tmp);
    cudaGetSymbolAddress((void**)&dW, g_W);
    cudaGetSymbolAddress((void**)&dT, g_T);
    cudaGetSymbolAddress((void**)&dGamma, g_gamma);
    cudaGetSymbolAddress((void**)&dSigma, g_sigma);
    cudaGetSymbolAddress((void**)&dAw, g_aw);
    cudaGetSymbolAddress((void**)&dCur, g_cur);
    cudaGetSymbolAddress((void**)&dCur2, g_cur2);
    cudaFuncSetAttribute(potrf_diag_kernel, cudaFuncAttributeMaxDynamicSharedMemorySize,
                         POTRF_SMEM);

    // ---- Layer A: M = I + Va^T Va ; factor ; Linv ; a_weight = Va Linv^T ----
    launch_gemm64(1, 0, Va, Nn, 0, Va, Nn, 0, dA, Nn, 0, Nn, Nn, Nn, 1.0f, 0.0f, 1.0f, 0, 1);
    chol_inplace(dA, dDinv, dTmp);
    build_linv(dA, dLinv, dDinv, dTmp);
    launch_gemm64(0, 1, Va, Nn, 0, dLinv, Nn, 0, dAw, Nn, 0, Nn, Nn, Nn, 1.0f, 0.0f, 0.0f, 0, 1);

    // first = x @ a_weight^T + ba  -> out
    gemm_batch_kernel<<<dim3(Nn / 128, BATCH / 128), 256>>>(x, Nn, dAw, Nn, ba, out, Nn, Nn,
                                                            0.0f, 0);
    set_identity_kernel<<<256, 256>>>(dGamma);
    cudaMemcpyAsync(dCur, x, (size_t)BATCH * Nn * sizeof(float), cudaMemcpyDeviceToDevice);

    float* cur = dCur;
    float* cur2 = dCur2;
    for (int i = 0; i < NL; ++i) {
        // T = gamma @ Linv^T ; W = V_i @ Linv^T
        launch_gemm64(0, 1, dGamma, Nn, 0, dLinv, Nn, 0, dT, Nn, 0, Nn, Nn, Nn, 1.0f, 0.0f, 0.0f, 0, 1);
        launch_gemm64(0, 1, Vin + (size_t)i * Nn * Nn, Nn, 0, dLinv, Nn, 0, dW, Nn, 0, Nn,
                      Nn, Nn, 1.0f, 0.0f, 0.0f, 0, 1);
        // cur = relu(cur @ W^T + b_i)
        gemm_batch_kernel<<<dim3(Nn / 128, BATCH / 128), 256>>>(
            cur, Nn, dW, Nn, bin + (size_t)i * Nn, cur2, Nn, Nn, 0.0f, 1);
        float* t = cur; cur = cur2; cur2 = t;
        // sigma update
        if (i == 0) {
            cudaMemcpyAsync(dSigma, dT, (size_t)Nn * Nn * sizeof(float),
                            cudaMemcpyDeviceToDevice);
        } else {
            launch_gemm64(0, 1, dSigma, Nn, 0, dSigma, Nn, 0, dA, Nn, 0, Nn, Nn, Nn, 1.0f, 0.0f, 0.0f, 0, 1);
            launch_gemm64(0, 1, dT, Nn, 0, dT, Nn, 0, dA, Nn, 0, Nn, Nn, Nn, 1.0f, 1.0f, 0.0f, 0, 1);
            chol_inplace(dA, dDinv, dTmp);
            tril_copy_kernel<<<256, 256>>>(dA, dSigma);
        }
        // gamma = T @ W^T
        launch_gemm64(0, 1, dT, Nn, 0, dW, Nn, 0, dGamma, Nn, 0, Nn, Nn, Nn, 1.0f, 0.0f, 0.0f, 0, 1);
        // M = I + 0.5 * W W^T ; factor ; Linv
        launch_gemm64(0, 1, dW, Nn, 0, dW, Nn, 0, dA, Nn, 0, Nn, Nn, Nn, 0.5f, 0.0f, 1.0f, 0, 1);
        chol_inplace(dA, dDinv, dTmp);
        build_linv(dA, dLinv, dDinv, dTmp);
    }

    // ---- Final layer B ----
    // Wb = Vb @ Linv^T  -> dW
    launch_gemm64(0, 1, Vb, Nn, 0, dLinv, Nn, 0, dW, Nn, 0, Nn, Nn, Nn, 1.0f, 0.0f, 0.0f, 0, 1);
    // left = a_weight @ sigma -> dT
    launch_gemm64(0, 0, dAw, Nn, 0, dSigma, Nn, 0, dT, Nn, 0, Nn, Nn, Nn, 1.0f, 0.0f, 0.0f, 0, 1);
    // M = I + left left^T ; factor ; Linv_sigma
    launch_gemm64(0, 1, dT, Nn, 0, dT, Nn, 0, dA, Nn, 0, Nn, Nn, Nn, 1.0f, 0.0f, 1.0f, 0, 1);
    chol_inplace(dA, dDinv, dTmp);
    build_linv(dA, dLinv, dDinv, dTmp);
    // b_weight = Linv_sigma^T @ Wb -> dT
    launch_gemm64(1, 0, dLinv, Nn, 0, dW, Nn, 0, dT, Nn, 0, Nn, Nn, Nn, 1.0f, 0.0f, 0.0f, 0, 1);
    // out += cur @ b_weight^T
    gemm_batch_kernel<<<dim3(Nn / 128, BATCH / 128), 256>>>(cur, Nn, dT, Nn, nullptr, out,
                                                            Nn, Nn, 1.0f, 0);
}

// round 7
// speedup vs baseline: 1.7583x; 1.7583x over previous
#include <cuda_runtime.h>
#include <cuda_bf16.h>
#include <cstdint>
#include <cstddef>

#define Nn 1024
#define BATCH 4096
#define NL 8
#define NB 128

// ---------------- device scratch (no allocations allowed) ----------------
__device__ float g_A[Nn * Nn];
__device__ float g_Linv[Nn * Nn];
__device__ float g_Dinv[8 * NB * NB];
__device__ float g_tmp[Nn * Nn];
__device__ float g_W[Nn * Nn];
__device__ float g_T[Nn * Nn];
__device__ float g_gamma[Nn * Nn];
__device__ float g_S[Nn * Nn];
__device__ float g_aw[Nn * Nn];
__device__ float g_cur[BATCH * Nn];
__device__ float g_cur2[BATCH * Nn];

// ================= bf16x3-split GEMM on legacy tensor cores (mma.sync) =================
// C[M,N] = alpha * op(A) * op(B)^T (+bias) (+beta*C) (+diagAdd on diag) (relu?)
// op = identity (TR=0, operand row r = src[r,:]) or transpose (TR=1, row r = src[:,r]).
// fp32 emulated: A = Ah + Am, B = Bh + Bm (bf16 hi/mid); C ~= Ah*Bh + Ah*Bm + Am*Bh.
// flags: 1 = relu, 2 = lowerOnly (skip tiles strictly above block diagonal).

#define SMS 72  // smem row stride in bf16 (64 data + 8 pad -> conflict-free)

__device__ __forceinline__ void mma16816(float* c, uint32_t a0, uint32_t a1, uint32_t a2,
                                         uint32_t a3, uint32_t b0, uint32_t b1) {
    asm volatile(
        "mma.sync.aligned.m16n8k16.row.col.f32.bf16.bf16.f32 "
        "{%0,%1,%2,%3},{%4,%5,%6,%7},{%8,%9},{%0,%1,%2,%3};\n"
        : "+f"(c[0]), "+f"(c[1]), "+f"(c[2]), "+f"(c[3])
        : "r"(a0), "r"(a1), "r"(a2), "r"(a3), "r"(b0), "r"(b1));
}

__device__ __forceinline__ void split2(float v, __nv_bfloat16& h, __nv_bfloat16& m) {
    h = __float2bfloat16(v);
    m = __float2bfloat16(v - __bfloat162float(h));
}

template <int TRA, int TRB>
__global__ __launch_bounds__(256) void gemm_mma(const float* __restrict__ A, int lda,
                                                const float* __restrict__ B, int ldb, int K,
                                                float* __restrict__ C, int ldc,
                                                const float* __restrict__ bias, float alpha,
                                                float beta, float diagAdd, int flags) {
    const int bi = blockIdx.y, bj = blockIdx.x;
    if ((flags & 2) && bj > bi) return;
    extern __shared__ __nv_bfloat16 sm[];
    __nv_bfloat16* Ah = sm;                 // [128][SMS]
    __nv_bfloat16* Am = Ah + 128 * SMS;
    __nv_bfloat16* Bh = Am + 128 * SMS;
    __nv_bfloat16* Bm = Bh + 128 * SMS;
    const int tid = threadIdx.x, wid = tid >> 5, lane = tid & 31;
    const int wy = wid >> 2, wx = wid & 3;  // 2 x 4 warp grid
    const int m0 = bi * 128, n0 = bj * 128;
    const int g = lane >> 2, tg = lane & 3;

    float acc[4][4][4];
#pragma unroll
    for (int i = 0; i < 4; ++i)
#pragma unroll
        for (int j = 0; j < 4; ++j)
#pragma unroll
            for (int q = 0; q < 4; ++q) acc[i][j][q] = 0.0f;

    for (int k0 = 0; k0 < K; k0 += 64) {
        // ---- load A tile (128 x 64) -> Ah/Am ----
        if (!TRA) {
#pragma unroll
            for (int it = 0; it < 8; ++it) {
                int idx = tid + it * 256;
                int r = idx >> 4, cq = (idx & 15) * 4;
                float4 v = *(const float4*)(A + (size_t)(m0 + r) * lda + k0 + cq);
                __nv_bfloat16 h0, h1, h2, h3, mm0, mm1, mm2, mm3;
                split2(v.x, h0, mm0); split2(v.y, h1, mm1);
                split2(v.z, h2, mm2); split2(v.w, h3, mm3);
                __nv_bfloat16* ph = Ah + r * SMS + cq;
                __nv_bfloat16* pm = Am + r * SMS + cq;
                ph[0] = h0; ph[1] = h1; ph[2] = h2; ph[3] = h3;
                pm[0] = mm0; pm[1] = mm1; pm[2] = mm2; pm[3] = mm3;
            }
        } else {
            const int r = tid >> 3, cbase = (tid & 7) * 8;
            const float* src = A + (size_t)(k0 + cbase) * lda + m0;
#pragma unroll
            for (int rr = 0; rr < 4; ++rr) {
                int row = r + rr * 32;
#pragma unroll
                for (int j = 0; j < 8; ++j) {
                    float v = src[(size_t)j * lda + row];
                    __nv_bfloat16 h, mm;
                    split2(v, h, mm);
                    Ah[row * SMS + cbase + j] = h;
                    Am[row * SMS + cbase + j] = mm;
                }
            }
        }
        // ---- load B tile (128 x 64) -> Bh/Bm ----
        if (!TRB) {
#pragma unroll
            for (int it = 0; it < 8; ++it) {
                int idx = tid + it * 256;
                int r = idx >> 4, cq = (idx & 15) * 4;
                float4 v = *(const float4*)(B + (size_t)(n0 + r) * ldb + k0 + cq);
                __nv_bfloat16 h0, h1, h2, h3, mm0, mm1, mm2, mm3;
                split2(v.x, h0, mm0); split2(v.y, h1, mm1);
                split2(v.z, h2, mm2); split2(v.w, h3, mm3);
                __nv_bfloat16* ph = Bh + r * SMS + cq;
                __nv_bfloat16* pm = Bm + r * SMS + cq;
                ph[0] = h0; ph[1] = h1; ph[2] = h2; ph[3] = h3;
                pm[0] = mm0; pm[1] = mm1; pm[2] = mm2; pm[3] = mm3;
            }
        } else {
            const int r = tid >> 3, cbase = (tid & 7) * 8;
            const float* src = B + (size_t)(k0 + cbase) * ldb + n0;
#pragma unroll
            for (int rr = 0; rr < 4; ++rr) {
                int row = r + rr * 32;
#pragma unroll
                for (int j = 0; j < 8; ++j) {
                    float v = src[(size_t)j * ldb + row];
                    __nv_bfloat16 h, mm;
                    split2(v, h, mm);
                    Bh[row * SMS + cbase + j] = h;
                    Bm[row * SMS + cbase + j] = mm;
                }
            }
        }
        __syncthreads();

        // ---- 3 split passes: Ah*Bh, Ah*Bm, Am*Bh ----
#pragma unroll
        for (int p = 0; p < 3; ++p) {
            const __nv_bfloat16* As = (p == 2) ? Am : Ah;
            const __nv_bfloat16* Bs = (p == 1) ? Bm : Bh;
#pragma unroll
            for (int kk = 0; kk < 4; ++kk) {
                uint32_t af[4][4], bf[4][2];
#pragma unroll
                for (int mt = 0; mt < 4; ++mt) {
                    int r = wy * 64 + mt * 16;
                    const __nv_bfloat16* p0 = As + (r + g) * SMS + kk * 16 + 2 * tg;
                    const __nv_bfloat16* p1 = As + (r + 8 + g) * SMS + kk * 16 + 2 * tg;
                    af[mt][0] = *(const uint32_t*)p0;
                    af[mt][1] = *(const uint32_t*)p1;
                    af[mt][2] = *(const uint32_t*)(p0 + 8);
                    af[mt][3] = *(const uint32_t*)(p1 + 8);
                }
#pragma unroll
                for (int nt = 0; nt < 4; ++nt) {
                    int r = wx * 32 + nt * 8 + g;
                    const __nv_bfloat16* p0 = Bs + r * SMS + kk * 16 + 2 * tg;
                    bf[nt][0] = *(const uint32_t*)p0;
                    bf[nt][1] = *(const uint32_t*)(p0 + 8);
                }
#pragma unroll
                for (int mt = 0; mt < 4; ++mt)
#pragma unroll
                    for (int nt = 0; nt < 4; ++nt)
                        mma16816(acc[mt][nt], af[mt][0], af[mt][1], af[mt][2], af[mt][3],
                                 bf[nt][0], bf[nt][1]);
            }
        }
        __syncthreads();
    }

    // ---- epilogue ----
#pragma unroll
    for (int mt = 0; mt < 4; ++mt) {
#pragma unroll
        for (int nt = 0; nt < 4; ++nt) {
#pragma unroll
            for (int half = 0; half < 2; ++half) {
                int r = m0 + wy * 64 + mt * 16 + g + half * 8;
                int c = n0 + wx * 32 + nt * 8 + 2 * tg;
                float v0 = alpha * acc[mt][nt][half * 2 + 0];
                float v1 = alpha * acc[mt][nt][half * 2 + 1];
                if (bias) { v0 += bias[c]; v1 += bias[c + 1]; }
                if (beta != 0.0f) {
                    v0 += beta * C[(size_t)r * ldc + c];
                    v1 += beta * C[(size_t)r * ldc + c + 1];
                }
                if (diagAdd != 0.0f) {
                    if (r == c) v0 += diagAdd;
                    if (r == c + 1) v1 += diagAdd;
                }
                if (flags & 1) { v0 = fmaxf(v0, 0.0f); v1 = fmaxf(v1, 0.0f); }
                *(float2*)(C + (size_t)r * ldc + c) = make_float2(v0, v1);
            }
        }
    }
}

// ================= potrf (128x128 diag block) + diag-block inverse =================
extern __shared__ float s_potrf[];
__global__ void potrf_diag_kernel(float* A, int lda, int k, float* Dinv) {
    float(*sL)[NB + 1] = (float(*)[NB + 1]) s_potrf;
    float(*sX)[NB + 1] = (float(*)[NB + 1])(s_potrf + NB * (NB + 1));
    const int tid = threadIdx.x;
    float* Ab = A + (size_t)k * NB * lda + (size_t)k * NB;
    for (int idx = tid; idx < NB * NB; idx += 256) {
        int r = idx >> 7, c = idx & (NB - 1);
        sL[r][c] = Ab[(size_t)r * lda + c];
        sX[r][c] = (r == c) ? 1.0f : 0.0f;
    }
    __syncthreads();
    const int tx = tid & 7, ty = tid >> 3;
    for (int j = 0; j < NB; ++j) {
        if (tid == 0) sL[j][j] = sqrtf(sL[j][j]);
        __syncthreads();
        float invd = 1.0f / sL[j][j];
        for (int i = j + 1 + tid; i < NB; i += 256) sL[i][j] *= invd;
        for (int c = tid; c <= j; c += 256) sX[j][c] *= invd;
        __syncthreads();
        for (int i = j + 1 + ty; i < NB; i += 32) {
            float lij = sL[i][j];
            for (int c = j + 1 + tx; c <= i; c += 8) sL[i][c] -= lij * sL[c][j];
            for (int c = tx; c <= j; c += 8) sX[i][c] -= lij * sX[j][c];
        }
        __syncthreads();
    }
    for (int idx = tid; idx < NB * NB; idx += 256) {
        int r = idx >> 7, c = idx & (NB - 1);
        Ab[(size_t)r * lda + c] = (c <= r) ? sL[r][c] : 0.0f;
        Dinv[idx] = sX[r][c];
    }
}

// ================= SIMT 64x64x16 SGEMM (chol internals / build_linv) =================
template <int TA, int TB>
__global__ void gemm64_kernel(const float* __restrict__ A, int lda, long long strA,
                              const float* __restrict__ B, int ldb, long long strB,
                              float* __restrict__ C, int ldc, long long strC, int K,
                              float alpha, float beta, float diagAdd, int lowerOnly) {
    const int bi = blockIdx.y, bj = blockIdx.x;
    if (lowerOnly && bj > bi) return;
    A += (long long)blockIdx.z * strA;
    B += (long long)blockIdx.z * strB;
    C += (long long)blockIdx.z * strC;
    __shared__ float As[16][68];
    __shared__ float Bs[16][68];
    const int tid = threadIdx.x;
    const int tx = tid & 7, ty = tid >> 3;
    const int row0 = bi * 64, col0 = bj * 64;
    float acc[4][8];
#pragma unroll
    for (int i = 0; i < 4; ++i)
#pragma unroll
        for (int j = 0; j < 8; ++j) acc[i][j] = 0.0f;

    for (int k0 = 0; k0 < K; k0 += 16) {
        if (TA == 0) {
#pragma unroll
            for (int r = 0; r < 2; ++r) {
                int idx = tid + r * 128;
                int m = idx >> 2, kq = (idx & 3) * 4;
                float4 v = *(const float4*)(A + (long long)(row0 + m) * lda + k0 + kq);
                As[kq + 0][m] = v.x; As[kq + 1][m] = v.y;
                As[kq + 2][m] = v.z; As[kq + 3][m] = v.w;
            }
        } else {
#pragma unroll
            for (int r = 0; r < 2; ++r) {
                int idx = tid + r * 128;
                int kk = idx >> 4, mq = (idx & 15) * 4;
                float4 v = *(const float4*)(A + (long long)(k0 + kk) * lda + row0 + mq);
                *(float4*)&As[kk][mq] = v;
            }
        }
        if (TB == 0) {
#pragma unroll
            for (int r = 0; r < 2; ++r) {
                int idx = tid + r * 128;
                int kk = idx >> 4, nq = (idx & 15) * 4;
                float4 v = *(const float4*)(B + (long long)(k0 + kk) * ldb + col0 + nq);
                *(float4*)&Bs[kk][nq] = v;
            }
        } else {
#pragma unroll
            for (int r = 0; r < 2; ++r) {
                int idx = tid + r * 128;
                int n = idx >> 2, kq = (idx & 3) * 4;
                float4 v = *(const float4*)(B + (long long)(col0 + n) * ldb + k0 + kq);
                Bs[kq + 0][n] = v.x; Bs[kq + 1][n] = v.y;
                Bs[kq + 2][n] = v.z; Bs[kq + 3][n] = v.w;
            }
        }
        __syncthreads();
#pragma unroll
        for (int kk = 0; kk < 16; ++kk) {
            float a[4], b[8];
            *(float4*)a = *(const float4*)&As[kk][ty * 4];
            *(float4*)b = *(const float4*)&Bs[kk][tx * 8];
            *(float4*)(b + 4) = *(const float4*)&Bs[kk][tx * 8 + 4];
#pragma unroll
            for (int i = 0; i < 4; ++i)
#pragma unroll
                for (int j = 0; j < 8; ++j) acc[i][j] += a[i] * b[j];
        }
        __syncthreads();
    }
#pragma unroll
    for (int i = 0; i < 4; ++i) {
        int r = row0 + ty * 4 + i;
#pragma unroll
        for (int j = 0; j < 8; ++j) {
            int c = col0 + tx * 8 + j;
            float v = alpha * acc[i][j];
            if (beta != 0.0f) v += beta * C[(long long)r * ldc + c];
            if (r == c) v += diagAdd;
            C[(long long)r * ldc + c] = v;
        }
    }
}

// ================= small utility kernels =================
__global__ void copy_panel_kernel(const float* __restrict__ src, float* __restrict__ dst,
                                  int rows, int ldd) {
    int total = rows * 32;
    for (int idx = blockIdx.x * blockDim.x + threadIdx.x; idx < total;
         idx += gridDim.x * blockDim.x) {
        int r = idx >> 5, q = idx & 31;
        *(float4*)(dst + (long long)r * ldd + q * 4) = *(const float4*)(src + r * 128 + q * 4);
    }
}

__global__ void place_dinv_kernel(float* __restrict__ Linv, const float* __restrict__ Dinv) {
    for (int idx = blockIdx.x * blockDim.x + threadIdx.x; idx < 8 * NB * NB;
         idx += gridDim.x * blockDim.x) {
        int k = idx >> 14;
        int rem = idx & (NB * NB - 1);
        int r = rem >> 7, c = rem & (NB - 1);
        Linv[(long long)(k * NB + r) * Nn + k * NB + c] = Dinv[idx];
    }
}

__global__ void transpose_kernel(const float* __restrict__ src, float* __restrict__ dst) {
    __shared__ float t[32][33];
    int bx = blockIdx.x * 32, by = blockIdx.y * 32;
    t[threadIdx.y][threadIdx.x] = src[(size_t)(by + threadIdx.y) * Nn + bx + threadIdx.x];
    __syncthreads();
    dst[(size_t)(bx + threadIdx.y) * Nn + by + threadIdx.x] = t[threadIdx.x][threadIdx.y];
}

// ================= host orchestration =================
static void launch_gemm64(int TA, int TB, const float* A, int lda, long long sA,
                          const float* B, int ldb, long long sB, float* C, int ldc,
                          long long sC, int M, int Ncols, int K, float alpha, float beta,
                          float diagAdd, int lowerOnly, int batch) {
    dim3 grid(Ncols / 64, M / 64, batch);
    if (TA == 0 && TB == 0)
        gemm64_kernel<0, 0><<<grid, 128>>>(A, lda, sA, B, ldb, sB, C, ldc, sC, K, alpha, beta, diagAdd, lowerOnly);
    else if (TA == 0 && TB == 1)
        gemm64_kernel<0, 1><<<grid, 128>>>(A, lda, sA, B, ldb, sB, C, ldc, sC, K, alpha, beta, diagAdd, lowerOnly);
    else if (TA == 1 && TB == 0)
        gemm64_kernel<1, 0><<<grid, 128>>>(A, lda, sA, B, ldb, sB, C, ldc, sC, K, alpha, beta, diagAdd, lowerOnly);
    else
        gemm64_kernel<1, 1><<<grid, 128>>>(A, lda, sA, B, ldb, sB, C, ldc, sC, K, alpha, beta, diagAdd, lowerOnly);
}

static const int POTRF_SMEM = 2 * NB * (NB + 1) * sizeof(float);
static const int MMA_SMEM = 4 * 128 * SMS * (int)sizeof(__nv_bfloat16);

static void chol_inplace(float* A, float* Dinv, float* tmp) {
    for (int k = 0; k < Nn / NB; ++k) {
        potrf_diag_kernel<<<1, 256, POTRF_SMEM>>>(A, Nn, k, Dinv + (size_t)k * NB * NB);
        int rem = Nn - (k + 1) * NB;
        if (rem > 0) {
            float* panel = A + (size_t)(k + 1) * NB * Nn + (size_t)k * NB;
            launch_gemm64(0, 1, panel, Nn, 0, Dinv + (size_t)k * NB * NB, NB, 0, tmp, NB, 0,
                          rem, NB, NB, 1.0f, 0.0f, 0.0f, 0, 1);
            copy_panel_kernel<<<64, 256>>>(tmp, panel, rem, Nn);
            float* At = A + (size_t)(k + 1) * NB * Nn + (size_t)(k + 1) * NB;
            launch_gemm64(0, 1, panel, Nn, 0, panel, Nn, 0, At, Nn, 0, rem, rem, NB, -1.0f,
                          1.0f, 0.0f, 1, 1);
        }
    }
}

static void build_linv(const float* A, float* Linv, const float* Dinv, float* tmp) {
    cudaMemsetAsync(Linv, 0, (size_t)Nn * Nn * sizeof(float));
    place_dinv_kernel<<<128, 256>>>(Linv, Dinv);
    for (int s = 128; s <= 512; s <<= 1) {
        int P = Nn / (2 * s);
        long long str = 2LL * s * (Nn + 1);
        launch_gemm64(0, 0, A + (long long)s * Nn, Nn, str, Linv, Nn, str, tmp, s,
                      (long long)s * s, s, s, s, 1.0f, 0.0f, 0.0f, 0, P);
        launch_gemm64(0, 0, Linv + (long long)s * (Nn + 1), Nn, str, tmp, s,
                      (long long)s * s, Linv + (long long)s * Nn, Nn, str, s, s, s, -1.0f,
                      0.0f, 0.0f, 0, P);
    }
}

static void tc00(const float* A, int lda, const float* B, int ldb, int M, int N, int K,
                 float* C, int ldc, const float* bias, float alpha, float beta, float dAdd,
                 int flags) {
    gemm_mma<0, 0><<<dim3(N / 128, M / 128), 256, MMA_SMEM>>>(A, lda, B, ldb, K, C, ldc,
                                                              bias, alpha, beta, dAdd, flags);
}
static void tc11(const float* A, int lda, const float* B, int ldb, int M, int N, int K,
                 float* C, int ldc, const float* bias, float alpha, float beta, float dAdd,
                 int flags) {
    gemm_mma<1, 1><<<dim3(N / 128, M / 128), 256, MMA_SMEM>>>(A, lda, B, ldb, K, C, ldc,
                                                              bias, alpha, beta, dAdd, flags);
}

extern "C" void kernel_launch(void* const* d_in, const int* in_sizes, int n_in, void* d_out,
                              int out_size) {
    const float* x = (const float*)d_in[0];
    const float* Va = (const float*)d_in[1];
    const float* ba = (const float*)d_in[2];
    const float* Vin = (const float*)d_in[3];
    const float* bin = (const float*)d_in[4];
    const float* Vb = (const float*)d_in[5];
    float* out = (float*)d_out;

    float *dA, *dLinv, *dDinv, *dTmp, *dW, *dT, *dGamma, *dS, *dAw, *dCur, *dCur2;
    cudaGetSymbolAddress((void**)&dA, g_A);
    cudaGetSymbolAddress((void**)&dLinv, g_Linv);
    cudaGetSymbolAddress((void**)&dDinv, g_Dinv);
    cudaGetSymbolAddress((void**)&dTmp, g_tmp);
    cudaGetSymbolAddress((void**)&dW, g_W);
    cudaGetSymbolAddress((void**)&dT, g_T);
    cudaGetSymbolAddress((void**)&dGamma, g_gamma);
    cudaGetSymbolAddress((void**)&dS, g_S);
    cudaGetSymbolAddress((void**)&dAw, g_aw);
    cudaGetSymbolAddress((void**)&dCur, g_cur);
    cudaGetSymbolAddress((void**)&dCur2, g_cur2);
    cudaFuncSetAttribute(potrf_diag_kernel, cudaFuncAttributeMaxDynamicSharedMemorySize,
                         POTRF_SMEM);
    cudaFuncSetAttribute(gemm_mma<0, 0>, cudaFuncAttributeMaxDynamicSharedMemorySize, MMA_SMEM);
    cudaFuncSetAttribute(gemm_mma<1, 1>, cudaFuncAttributeMaxDynamicSharedMemorySize, MMA_SMEM);

    // ---- Layer A: M = I + Va^T Va ; factor ; Linv ; a_weight = Va Linv^T ----
    tc11(Va, Nn, Va, Nn, Nn, Nn, Nn, dA, Nn, nullptr, 1.0f, 0.0f, 1.0f, 2);
    chol_inplace(dA, dDinv, dTmp);
    build_linv(dA, dLinv, dDinv, dTmp);
    tc00(Va, Nn, dLinv, Nn, Nn, Nn, Nn, dAw, Nn, nullptr, 1.0f, 0.0f, 0.0f, 0);

    // first = x @ a_weight^T + ba -> out
    tc00(x, Nn, dAw, Nn, BATCH, Nn, Nn, out, Nn, ba, 1.0f, 0.0f, 0.0f, 0);
    cudaMemcpyAsync(dCur, x, (size_t)BATCH * Nn * sizeof(float), cudaMemcpyDeviceToDevice);

    float* cur = dCur;
    float* cur2 = dCur2;
    for (int i = 0; i < NL; ++i) {
        // T = gamma @ Linv^T  (layer 0: gamma = I -> T = Linv^T)
        if (i == 0)
            transpose_kernel<<<dim3(32, 32), dim3(32, 32)>>>(dLinv, dT);
        else
            tc00(dGamma, Nn, dLinv, Nn, Nn, Nn, Nn, dT, Nn, nullptr, 1.0f, 0.0f, 0.0f, 0);
        // W = V_i @ Linv^T
        tc00(Vin + (size_t)i * Nn * Nn, Nn, dLinv, Nn, Nn, Nn, Nn, dW, Nn, nullptr, 1.0f,
             0.0f, 0.0f, 0);
        // cur = relu(cur @ W^T + b_i)
        tc00(cur, Nn, dW, Nn, BATCH, Nn, Nn, cur2, Nn, bin + (size_t)i * Nn, 1.0f, 0.0f,
             0.0f, 1);
        { float* t = cur; cur = cur2; cur2 = t; }
        // S += T T^T  (symmetric accumulator; replaces per-layer sigma choleskys)
        tc00(dT, Nn, dT, Nn, Nn, Nn, Nn, dS, Nn, nullptr, 1.0f, (i == 0) ? 0.0f : 1.0f,
             0.0f, 0);
        // gamma = T @ W^T
        tc00(dT, Nn, dW, Nn, Nn, Nn, Nn, dGamma, Nn, nullptr, 1.0f, 0.0f, 0.0f, 0);
        // M = I + 0.5 W W^T ; factor ; Linv
        tc00(dW, Nn, dW, Nn, Nn, Nn, Nn, dA, Nn, nullptr, 0.5f, 0.0f, 1.0f, 2);
        chol_inplace(dA, dDinv, dTmp);
        build_linv(dA, dLinv, dDinv, dTmp);
    }

    // ---- Final layer B ----
    // Wb = Vb @ Linv^T -> dGamma (gamma is dead here)
    tc00(Vb, Nn, dLinv, Nn, Nn, Nn, Nn, dGamma, Nn, nullptr, 1.0f, 0.0f, 0.0f, 0);
    // U = aw @ S -> dT  (S full symmetric: row n of op(B)=S gives S[n,:])
    tc00(dAw, Nn, dS, Nn, Nn, Nn, Nn, dT, Nn, nullptr, 1.0f, 0.0f, 0.0f, 0);
    // M = I + U aw^T (= I + aw S aw^T) ; factor ; Linv_sigma
    tc00(dT, Nn, dAw, Nn, Nn, Nn, Nn, dA, Nn, nullptr, 1.0f, 0.0f, 1.0f, 2);
    chol_inplace(dA, dDinv, dTmp);
    build_linv(dA, dLinv, dDinv, dTmp);
    // b_weight = Linv_sigma^T @ Wb -> dW
    tc11(dLinv, Nn, dGamma, Nn, Nn, Nn, Nn, dW, Nn, nullptr, 1.0f, 0.0f, 0.0f, 0);
    // out += cur @ b_weight^T
    tc00(cur, Nn, dW, Nn, BATCH, Nn, Nn, out, Nn, nullptr, 1.0f, 1.0f, 0.0f, 0);
}

// round 8
// speedup vs baseline: 1.8465x; 1.0501x over previous
#include <cuda_runtime.h>
#include <cuda_bf16.h>
#include <cstdint>
#include <cstddef>

#define Nn 1024
#define BATCH 4096
#define NL 8
#define NB 128

// ---------------- device scratch (no allocations allowed) ----------------
__device__ float g_A[Nn * Nn];
__device__ float g_Linv[Nn * Nn];
__device__ float g_Dinv[8 * NB * NB];
__device__ float g_tmp[Nn * Nn];
__device__ float g_W[Nn * Nn];
__device__ float g_T[Nn * Nn];
__device__ float g_gamma[Nn * Nn];
__device__ float g_S[Nn * Nn];
__device__ float g_aw[Nn * Nn];
__device__ float g_cur[BATCH * Nn];
__device__ float g_cur2[BATCH * Nn];

// ================= bf16x3-split GEMM on tensor cores (mma.sync), pipelined ============
// C[M,N] = alpha * op(A) * op(B)^T (+bias) (+beta*C) (+diagAdd on diag) (relu?)
// TR=0: operand row r = src[r,:].  TR=1: operand row r = src[:,r].
// fp32 emulated: X = Xh + Xm (bf16 hi/mid); C ~= Ah*Bh + Ah*Bm + Am*Bh.
// flags: 1 = relu, 2 = lowerOnly (skip 64x128 tiles strictly above the diagonal).
// Tile: BM=64, BN=128, BK=64; 256 threads (8 warps as 2x4, warp tile 32x32);
// double-buffered smem, software-pipelined global loads.

#define SMS 72  // smem row stride in bf16 (64 data + 8 pad -> conflict-free)
// per-stage smem layout (bf16 elems): Ah[64*72]=4608, Am, Bh[128*72]=9216, Bm
#define STG_ELEMS 27648
static const int MMA_SMEM = 2 * STG_ELEMS * (int)sizeof(__nv_bfloat16);  // 110592

__device__ __forceinline__ void mma16816(float* c, uint32_t a0, uint32_t a1, uint32_t a2,
                                         uint32_t a3, uint32_t b0, uint32_t b1) {
    asm volatile(
        "mma.sync.aligned.m16n8k16.row.col.f32.bf16.bf16.f32 "
        "{%0,%1,%2,%3},{%4,%5,%6,%7},{%8,%9},{%0,%1,%2,%3};\n"
        : "+f"(c[0]), "+f"(c[1]), "+f"(c[2]), "+f"(c[3])
        : "r"(a0), "r"(a1), "r"(a2), "r"(a3), "r"(b0), "r"(b1));
}

__device__ __forceinline__ void split2(float v, __nv_bfloat16& h, __nv_bfloat16& m) {
    h = __float2bfloat16(v);
    m = __float2bfloat16(v - __bfloat162float(h));
}

template <int TRA, int TRB>
__global__ __launch_bounds__(256, 2) void gemm_mma(
    const float* __restrict__ A, int lda, long long strA, const float* __restrict__ B,
    int ldb, long long strB, int K, float* __restrict__ C, int ldc, long long strC,
    const float* __restrict__ bias, float alpha, float beta, float diagAdd, int flags) {
    const int bi = blockIdx.y, bj = blockIdx.x;
    if ((flags & 2) && 2 * bj > bi) return;
    A += (long long)blockIdx.z * strA;
    B += (long long)blockIdx.z * strB;
    C += (long long)blockIdx.z * strC;
    extern __shared__ __nv_bfloat16 sm[];
    const int tid = threadIdx.x, wid = tid >> 5, lane = tid & 31;
    const int wy = wid >> 2, wx = wid & 3;  // 2 x 4 warp grid
    const int g = lane >> 2, tg = lane & 3;
    const int m0 = bi * 64, n0 = bj * 128;

    float aReg[16], bReg[32];
    float acc[2][4][4];
#pragma unroll
    for (int i = 0; i < 2; ++i)
#pragma unroll
        for (int j = 0; j < 4; ++j)
#pragma unroll
            for (int q = 0; q < 4; ++q) acc[i][j][q] = 0.0f;

    const int T = K >> 6;

    auto loadT = [&](int t) {
        const int k0 = t << 6;
        if (!TRA) {
#pragma unroll
            for (int it = 0; it < 4; ++it) {
                int idx = tid + it * 256;
                int r = idx >> 4, q = (idx & 15) << 2;
                *(float4*)(aReg + it * 4) =
                    *(const float4*)(A + (size_t)(m0 + r) * lda + k0 + q);
            }
        } else {
            const int r = tid & 63, cb = (tid >> 6) << 4;
            const float* src = A + (size_t)(k0 + cb) * lda + m0 + r;
#pragma unroll
            for (int j = 0; j < 16; ++j) aReg[j] = src[(size_t)j * lda];
        }
        if (!TRB) {
#pragma unroll
            for (int it = 0; it < 8; ++it) {
                int idx = tid + it * 256;
                int r = idx >> 4, q = (idx & 15) << 2;
                *(float4*)(bReg + it * 4) =
                    *(const float4*)(B + (size_t)(n0 + r) * ldb + k0 + q);
            }
        } else {
            const int r = tid & 127, cb = (tid >> 7) << 5;
            const float* src = B + (size_t)(k0 + cb) * ldb + n0 + r;
#pragma unroll
            for (int j = 0; j < 32; ++j) bReg[j] = src[(size_t)j * ldb];
        }
    };

    auto storeT = [&](int st) {
        __nv_bfloat16* Ah = sm + st * STG_ELEMS;
        __nv_bfloat16* Am = Ah + 4608;
        __nv_bfloat16* Bh = Ah + 9216;
        __nv_bfloat16* Bm = Ah + 18432;
        if (!TRA) {
#pragma unroll
            for (int it = 0; it < 4; ++it) {
                int idx = tid + it * 256;
                int r = idx >> 4, q = (idx & 15) << 2;
                uint32_t hp[2], mp[2];
#pragma unroll
                for (int w = 0; w < 2; ++w) {
                    __nv_bfloat16 h0, h1, mq0, mq1;
                    split2(aReg[it * 4 + 2 * w], h0, mq0);
                    split2(aReg[it * 4 + 2 * w + 1], h1, mq1);
                    hp[w] = (uint32_t)__bfloat16_as_ushort(h0) |
                            ((uint32_t)__bfloat16_as_ushort(h1) << 16);
                    mp[w] = (uint32_t)__bfloat16_as_ushort(mq0) |
                            ((uint32_t)__bfloat16_as_ushort(mq1) << 16);
                }
                *(uint2*)(Ah + r * SMS + q) = make_uint2(hp[0], hp[1]);
                *(uint2*)(Am + r * SMS + q) = make_uint2(mp[0], mp[1]);
            }
        } else {
            const int r = tid & 63, cb = (tid >> 6) << 4;
#pragma unroll
            for (int j = 0; j < 16; ++j) {
                __nv_bfloat16 h, m;
                split2(aReg[j], h, m);
                Ah[r * SMS + cb + j] = h;
                Am[r * SMS + cb + j] = m;
            }
        }
        if (!TRB) {
#pragma unroll
            for (int it = 0; it < 8; ++it) {
                int idx = tid + it * 256;
                int r = idx >> 4, q = (idx & 15) << 2;
                uint32_t hp[2], mp[2];
#pragma unroll
                for (int w = 0; w < 2; ++w) {
                    __nv_bfloat16 h0, h1, mq0, mq1;
                    split2(bReg[it * 4 + 2 * w], h0, mq0);
                    split2(bReg[it * 4 + 2 * w + 1], h1, mq1);
                    hp[w] = (uint32_t)__bfloat16_as_ushort(h0) |
                            ((uint32_t)__bfloat16_as_ushort(h1) << 16);
                    mp[w] = (uint32_t)__bfloat16_as_ushort(mq0) |
                            ((uint32_t)__bfloat16_as_ushort(mq1) << 16);
                }
                *(uint2*)(Bh + r * SMS + q) = make_uint2(hp[0], hp[1]);
                *(uint2*)(Bm + r * SMS + q) = make_uint2(mp[0], mp[1]);
            }
        } else {
            const int r = tid & 127, cb = (tid >> 7) << 5;
#pragma unroll
            for (int j = 0; j < 32; ++j) {
                __nv_bfloat16 h, m;
                split2(bReg[j], h, m);
                Bh[r * SMS + cb + j] = h;
                Bm[r * SMS + cb + j] = m;
            }
        }
    };

    auto compute = [&](int st) {
        const __nv_bfloat16* base = sm + st * STG_ELEMS;
#pragma unroll
        for (int p = 0; p < 3; ++p) {
            const __nv_bfloat16* As = base + (p == 2 ? 4608 : 0);
            const __nv_bfloat16* Bs = base + (p == 1 ? 18432 : 9216);
#pragma unroll
            for (int kk = 0; kk < 4; ++kk) {
                uint32_t af[2][4], bf[4][2];
#pragma unroll
                for (int mt = 0; mt < 2; ++mt) {
                    const __nv_bfloat16* p0 =
                        As + (wy * 32 + mt * 16 + g) * SMS + kk * 16 + 2 * tg;
                    const __nv_bfloat16* p1 = p0 + 8 * SMS;
                    af[mt][0] = *(const uint32_t*)p0;
                    af[mt][1] = *(const uint32_t*)p1;
                    af[mt][2] = *(const uint32_t*)(p0 + 8);
                    af[mt][3] = *(const uint32_t*)(p1 + 8);
                }
#pragma unroll
                for (int nt = 0; nt < 4; ++nt) {
                    const __nv_bfloat16* p0 =
                        Bs + (wx * 32 + nt * 8 + g) * SMS + kk * 16 + 2 * tg;
                    bf[nt][0] = *(const uint32_t*)p0;
                    bf[nt][1] = *(const uint32_t*)(p0 + 8);
                }
#pragma unroll
                for (int mt = 0; mt < 2; ++mt)
#pragma unroll
                    for (int nt = 0; nt < 4; ++nt)
                        mma16816(acc[mt][nt], af[mt][0], af[mt][1], af[mt][2], af[mt][3],
                                 bf[nt][0], bf[nt][1]);
            }
        }
    };

    loadT(0);
    storeT(0);
    __syncthreads();
    for (int t = 0; t < T; ++t) {
        if (t + 1 < T) loadT(t + 1);
        compute(t & 1);
        if (t + 1 < T) storeT((t + 1) & 1);
        __syncthreads();
    }

    // ---- epilogue ----
#pragma unroll
    for (int mt = 0; mt < 2; ++mt) {
#pragma unroll
        for (int nt = 0; nt < 4; ++nt) {
#pragma unroll
            for (int half = 0; half < 2; ++half) {
                int r = m0 + wy * 32 + mt * 16 + g + half * 8;
                int c = n0 + wx * 32 + nt * 8 + 2 * tg;
                float v0 = alpha * acc[mt][nt][half * 2 + 0];
                float v1 = alpha * acc[mt][nt][half * 2 + 1];
                if (bias) { v0 += bias[c]; v1 += bias[c + 1]; }
                if (beta != 0.0f) {
                    v0 += beta * C[(size_t)r * ldc + c];
                    v1 += beta * C[(size_t)r * ldc + c + 1];
                }
                if (diagAdd != 0.0f) {
                    if (r == c) v0 += diagAdd;
                    if (r == c + 1) v1 += diagAdd;
                }
                if (flags & 1) { v0 = fmaxf(v0, 0.0f); v1 = fmaxf(v1, 0.0f); }
                *(float2*)(C + (size_t)r * ldc + c) = make_float2(v0, v1);
            }
        }
    }
}

// ================= potrf (128x128 diag block) + diag-block inverse =================
extern __shared__ float s_potrf[];
__global__ void potrf_diag_kernel(float* A, int lda, int k, float* Dinv) {
    float(*sL)[NB + 1] = (float(*)[NB + 1]) s_potrf;
    float(*sX)[NB + 1] = (float(*)[NB + 1])(s_potrf + NB * (NB + 1));
    const int tid = threadIdx.x;
    float* Ab = A + (size_t)k * NB * lda + (size_t)k * NB;
    for (int idx = tid; idx < NB * NB; idx += 256) {
        int r = idx >> 7, c = idx & (NB - 1);
        sL[r][c] = Ab[(size_t)r * lda + c];
        sX[r][c] = (r == c) ? 1.0f : 0.0f;
    }
    __syncthreads();
    const int tx = tid & 7, ty = tid >> 3;
    for (int j = 0; j < NB; ++j) {
        if (tid == 0) sL[j][j] = sqrtf(sL[j][j]);
        __syncthreads();
        float invd = 1.0f / sL[j][j];
        for (int i = j + 1 + tid; i < NB; i += 256) sL[i][j] *= invd;
        for (int c = tid; c <= j; c += 256) sX[j][c] *= invd;
        __syncthreads();
        for (int i = j + 1 + ty; i < NB; i += 32) {
            float lij = sL[i][j];
            for (int c = j + 1 + tx; c <= i; c += 8) sL[i][c] -= lij * sL[c][j];
            for (int c = tx; c <= j; c += 8) sX[i][c] -= lij * sX[j][c];
        }
        __syncthreads();
    }
    for (int idx = tid; idx < NB * NB; idx += 256) {
        int r = idx >> 7, c = idx & (NB - 1);
        Ab[(size_t)r * lda + c] = (c <= r) ? sL[r][c] : 0.0f;
        Dinv[idx] = sX[r][c];
    }
}

// ================= small utility kernels =================
__global__ void place_dinv_kernel(float* __restrict__ Linv, const float* __restrict__ Dinv) {
    for (int idx = blockIdx.x * blockDim.x + threadIdx.x; idx < 8 * NB * NB;
         idx += gridDim.x * blockDim.x) {
        int k = idx >> 14;
        int rem = idx & (NB * NB - 1);
        int r = rem >> 7, c = rem & (NB - 1);
        Linv[(long long)(k * NB + r) * Nn + k * NB + c] = Dinv[idx];
    }
}

__global__ void transpose_kernel(const float* __restrict__ src, float* __restrict__ dst) {
    __shared__ float t[32][33];
    int bx = blockIdx.x * 32, by = blockIdx.y * 32;
    t[threadIdx.y][threadIdx.x] = src[(size_t)(by + threadIdx.y) * Nn + bx + threadIdx.x];
    __syncthreads();
    dst[(size_t)(bx + threadIdx.y) * Nn + by + threadIdx.x] = t[threadIdx.x][threadIdx.y];
}

// ================= host orchestration =================
template <int TRA, int TRB>
static void gm(const float* A, int lda, long long sA, const float* B, int ldb, long long sB,
               int K, float* C, int ldc, long long sC, int M, int N, const float* bias,
               float alpha, float beta, float dAdd, int flags, int batch) {
    gemm_mma<TRA, TRB><<<dim3(N / 128, M / 64, batch), 256, MMA_SMEM>>>(
        A, lda, sA, B, ldb, sB, K, C, ldc, sC, bias, alpha, beta, dAdd, flags);
}

static const int POTRF_SMEM = 2 * NB * (NB + 1) * sizeof(float);

static void chol_inplace(float* A, float* Dinv) {
    for (int k = 0; k < Nn / NB; ++k) {
        potrf_diag_kernel<<<1, 256, POTRF_SMEM>>>(A, Nn, k, Dinv + (size_t)k * NB * NB);
        int rem = Nn - (k + 1) * NB;
        if (rem > 0) {
            float* panel = A + (size_t)(k + 1) * NB * Nn + (size_t)k * NB;
            // panel := panel * Dinv^T  (in place; each block reads its A-rows fully
            // into smem before the epilogue writes the same rows)
            gm<0, 0>(panel, Nn, 0, Dinv + (size_t)k * NB * NB, NB, 0, NB, panel, Nn, 0,
                     rem, NB, nullptr, 1.0f, 0.0f, 0.0f, 0, 1);
            // trailing syrk (lower tiles only): At -= panel * panel^T
            float* At = A + (size_t)(k + 1) * NB * Nn + (size_t)(k + 1) * NB;
            gm<0, 0>(panel, Nn, 0, panel, Nn, 0, NB, At, Nn, 0, rem, rem, nullptr, -1.0f,
                     1.0f, 0.0f, 2, 1);
        }
    }
}

static void build_linv(const float* A, float* Linv, const float* Dinv, float* tmp) {
    cudaMemsetAsync(Linv, 0, (size_t)Nn * Nn * sizeof(float));
    place_dinv_kernel<<<128, 256>>>(Linv, Dinv);
    for (int s = 128; s <= 512; s <<= 1) {
        int P = Nn / (2 * s);
        long long str = 2LL * s * (Nn + 1);
        // X1 = B_block * Ainv  (C = A*B -> TRB=1)
        gm<0, 1>(A + (long long)s * Nn, Nn, str, Linv, Nn, str, s, tmp, s, (long long)s * s,
                 s, s, nullptr, 1.0f, 0.0f, 0.0f, 0, P);
        // Linv_21 = -Cinv * X1
        gm<0, 1>(Linv + (long long)s * (Nn + 1), Nn, str, tmp, s, (long long)s * s, s,
                 Linv + (long long)s * Nn, Nn, str, s, s, nullptr, -1.0f, 0.0f, 0.0f, 0, P);
    }
}

extern "C" void kernel_launch(void* const* d_in, const int* in_sizes, int n_in, void* d_out,
                              int out_size) {
    const float* x = (const float*)d_in[0];
    const float* Va = (const float*)d_in[1];
    const float* ba = (const float*)d_in[2];
    const float* Vin = (const float*)d_in[3];
    const float* bin = (const float*)d_in[4];
    const float* Vb = (const float*)d_in[5];
    float* out = (float*)d_out;

    float *dA, *dLinv, *dDinv, *dTmp, *dW, *dT, *dGamma, *dS, *dAw, *dCur, *dCur2;
    cudaGetSymbolAddress((void**)&dA, g_A);
    cudaGetSymbolAddress((void**)&dLinv, g_Linv);
    cudaGetSymbolAddress((void**)&dDinv, g_Dinv);
    cudaGetSymbolAddress((void**)&dTmp, g_tmp);
    cudaGetSymbolAddress((void**)&dW, g_W);
    cudaGetSymbolAddress((void**)&dT, g_T);
    cudaGetSymbolAddress((void**)&dGamma, g_gamma);
    cudaGetSymbolAddress((void**)&dS, g_S);
    cudaGetSymbolAddress((void**)&dAw, g_aw);
    cudaGetSymbolAddress((void**)&dCur, g_cur);
    cudaGetSymbolAddress((void**)&dCur2, g_cur2);
    cudaFuncSetAttribute(potrf_diag_kernel, cudaFuncAttributeMaxDynamicSharedMemorySize,
                         POTRF_SMEM);
    cudaFuncSetAttribute(gemm_mma<0, 0>, cudaFuncAttributeMaxDynamicSharedMemorySize,
                         MMA_SMEM);
    cudaFuncSetAttribute(gemm_mma<0, 1>, cudaFuncAttributeMaxDynamicSharedMemorySize,
                         MMA_SMEM);
    cudaFuncSetAttribute(gemm_mma<1, 1>, cudaFuncAttributeMaxDynamicSharedMemorySize,
                         MMA_SMEM);

    // ---- Layer A: M = I + Va^T Va ; factor ; Linv ; a_weight = Va Linv^T ----
    gm<1, 1>(Va, Nn, 0, Va, Nn, 0, Nn, dA, Nn, 0, Nn, Nn, nullptr, 1.0f, 0.0f, 1.0f, 2, 1);
    chol_inplace(dA, dDinv);
    build_linv(dA, dLinv, dDinv, dTmp);
    gm<0, 0>(Va, Nn, 0, dLinv, Nn, 0, Nn, dAw, Nn, 0, Nn, Nn, nullptr, 1.0f, 0.0f, 0.0f, 0, 1);

    // first = x @ a_weight^T + ba -> out
    gm<0, 0>(x, Nn, 0, dAw, Nn, 0, Nn, out, Nn, 0, BATCH, Nn, ba, 1.0f, 0.0f, 0.0f, 0, 1);
    cudaMemcpyAsync(dCur, x, (size_t)BATCH * Nn * sizeof(float), cudaMemcpyDeviceToDevice);

    float* cur = dCur;
    float* cur2 = dCur2;
    for (int i = 0; i < NL; ++i) {
        // T = gamma @ Linv^T  (layer 0: gamma = I -> T = Linv^T)
        if (i == 0)
            transpose_kernel<<<dim3(32, 32), dim3(32, 32)>>>(dLinv, dT);
        else
            gm<0, 0>(dGamma, Nn, 0, dLinv, Nn, 0, Nn, dT, Nn, 0, Nn, Nn, nullptr, 1.0f,
                     0.0f, 0.0f, 0, 1);
        // W = V_i @ Linv^T
        gm<0, 0>(Vin + (size_t)i * Nn * Nn, Nn, 0, dLinv, Nn, 0, Nn, dW, Nn, 0, Nn, Nn,
                 nullptr, 1.0f, 0.0f, 0.0f, 0, 1);
        // cur = relu(cur @ W^T + b_i)
        gm<0, 0>(cur, Nn, 0, dW, Nn, 0, Nn, cur2, Nn, 0, BATCH, Nn, bin + (size_t)i * Nn,
                 1.0f, 0.0f, 0.0f, 1, 1);
        { float* t = cur; cur = cur2; cur2 = t; }
        // S += T T^T (full symmetric accumulator; replaces per-layer sigma choleskys)
        gm<0, 0>(dT, Nn, 0, dT, Nn, 0, Nn, dS, Nn, 0, Nn, Nn, nullptr, 1.0f,
                 (i == 0) ? 0.0f : 1.0f, 0.0f, 0, 1);
        // gamma = T @ W^T
        gm<0, 0>(dT, Nn, 0, dW, Nn, 0, Nn, dGamma, Nn, 0, Nn, Nn, nullptr, 1.0f, 0.0f,
                 0.0f, 0, 1);
        // M = I + 0.5 W W^T ; factor ; Linv
        gm<0, 0>(dW, Nn, 0, dW, Nn, 0, Nn, dA, Nn, 0, Nn, Nn, nullptr, 0.5f, 0.0f, 1.0f, 2, 1);
        chol_inplace(dA, dDinv);
        build_linv(dA, dLinv, dDinv, dTmp);
    }

    // ---- Final layer B ----
    // Wb = Vb @ Linv^T -> dGamma (gamma dead here)
    gm<0, 0>(Vb, Nn, 0, dLinv, Nn, 0, Nn, dGamma, Nn, 0, Nn, Nn, nullptr, 1.0f, 0.0f, 0.0f, 0, 1);
    // U = aw @ S -> dT  (S full symmetric)
    gm<0, 0>(dAw, Nn, 0, dS, Nn, 0, Nn, dT, Nn, 0, Nn, Nn, nullptr, 1.0f, 0.0f, 0.0f, 0, 1);
    // M = I + U aw^T (= I + aw S aw^T) ; factor ; Linv_sigma
    gm<0, 0>(dT, Nn, 0, dAw, Nn, 0, Nn, dA, Nn, 0, Nn, Nn, nullptr, 1.0f, 0.0f, 1.0f, 2, 1);
    chol_inplace(dA, dDinv);
    build_linv(dA, dLinv, dDinv, dTmp);
    // b_weight = Linv_sigma^T @ Wb -> dW
    gm<1, 1>(dLinv, Nn, 0, dGamma, Nn, 0, Nn, dW, Nn, 0, Nn, Nn, nullptr, 1.0f, 0.0f, 0.0f, 0, 1);
    // out += cur @ b_weight^T
    gm<0, 0>(cur, Nn, 0, dW, Nn, 0, Nn, out, Nn, 0, BATCH, Nn, nullptr, 1.0f, 1.0f, 0.0f, 0, 1);
}

// round 9
// speedup vs baseline: 2.7273x; 1.4770x over previous
#include <cuda_runtime.h>
#include <cuda_bf16.h>
#include <cstdint>
#include <cstddef>

#define Nn 1024
#define BATCH 4096
#define NL 8
#define NB 128

// ---------------- device scratch (no allocations allowed) ----------------
__device__ float g_A[Nn * Nn];
__device__ float g_Linv[Nn * Nn];
__device__ float g_Dinv[8 * NB * NB];
__device__ float g_tmp[Nn * Nn];
__device__ float g_W[Nn * Nn];
__device__ float g_T[Nn * Nn];
__device__ float g_gamma[Nn * Nn];
__device__ float g_S[Nn * Nn];
__device__ float g_aw[Nn * Nn];
__device__ float g_cur[BATCH * Nn];
__device__ float g_cur2[BATCH * Nn];

// ================= bf16x3-split GEMM on tensor cores (mma.sync), pipelined ============
// C[M,N] = alpha * op(A) * op(B)^T (+bias) (+beta*C) (+diagAdd on diag) (relu?)
// TR=0: operand row r = src[r,:].  TR=1: operand row r = src[:,r].
// fp32 emulated: X = Xh + Xm (bf16 hi/mid); C ~= Ah*Bh + Ah*Bm + Am*Bh.
// flags: 1 = relu, 2 = lowerOnly (skip 64x128 tiles strictly above the diagonal).

#define SMS 72  // smem row stride in bf16 (64 data + 8 pad -> conflict-free)
#define STG_ELEMS 27648
static const int MMA_SMEM = 2 * STG_ELEMS * (int)sizeof(__nv_bfloat16);  // 110592

__device__ __forceinline__ void mma16816(float* c, uint32_t a0, uint32_t a1, uint32_t a2,
                                         uint32_t a3, uint32_t b0, uint32_t b1) {
    asm volatile(
        "mma.sync.aligned.m16n8k16.row.col.f32.bf16.bf16.f32 "
        "{%0,%1,%2,%3},{%4,%5,%6,%7},{%8,%9},{%0,%1,%2,%3};\n"
        : "+f"(c[0]), "+f"(c[1]), "+f"(c[2]), "+f"(c[3])
        : "r"(a0), "r"(a1), "r"(a2), "r"(a3), "r"(b0), "r"(b1));
}

__device__ __forceinline__ void split2(float v, __nv_bfloat16& h, __nv_bfloat16& m) {
    h = __float2bfloat16(v);
    m = __float2bfloat16(v - __bfloat162float(h));
}

template <int TRA, int TRB>
__global__ __launch_bounds__(256, 2) void gemm_mma(
    const float* __restrict__ A, int lda, long long strA, const float* __restrict__ B,
    int ldb, long long strB, int K, float* __restrict__ C, int ldc, long long strC,
    const float* __restrict__ bias, float alpha, float beta, float diagAdd, int flags) {
    const int bi = blockIdx.y, bj = blockIdx.x;
    if ((flags & 2) && 2 * bj > bi) return;
    A += (long long)blockIdx.z * strA;
    B += (long long)blockIdx.z * strB;
    C += (long long)blockIdx.z * strC;
    extern __shared__ __nv_bfloat16 sm[];
    const int tid = threadIdx.x, wid = tid >> 5, lane = tid & 31;
    const int wy = wid >> 2, wx = wid & 3;  // 2 x 4 warp grid
    const int g = lane >> 2, tg = lane & 3;
    const int m0 = bi * 64, n0 = bj * 128;

    float aReg[16], bReg[32];
    float acc[2][4][4];
#pragma unroll
    for (int i = 0; i < 2; ++i)
#pragma unroll
        for (int j = 0; j < 4; ++j)
#pragma unroll
            for (int q = 0; q < 4; ++q) acc[i][j][q] = 0.0f;

    const int T = K >> 6;

    auto loadT = [&](int t) {
        const int k0 = t << 6;
        if (!TRA) {
#pragma unroll
            for (int it = 0; it < 4; ++it) {
                int idx = tid + it * 256;
                int r = idx >> 4, q = (idx & 15) << 2;
                *(float4*)(aReg + it * 4) =
                    *(const float4*)(A + (size_t)(m0 + r) * lda + k0 + q);
            }
        } else {
            const int r = tid & 63, cb = (tid >> 6) << 4;
            const float* src = A + (size_t)(k0 + cb) * lda + m0 + r;
#pragma unroll
            for (int j = 0; j < 16; ++j) aReg[j] = src[(size_t)j * lda];
        }
        if (!TRB) {
#pragma unroll
            for (int it = 0; it < 8; ++it) {
                int idx = tid + it * 256;
                int r = idx >> 4, q = (idx & 15) << 2;
                *(float4*)(bReg + it * 4) =
                    *(const float4*)(B + (size_t)(n0 + r) * ldb + k0 + q);
            }
        } else {
            const int r = tid & 127, cb = (tid >> 7) << 5;
            const float* src = B + (size_t)(k0 + cb) * ldb + n0 + r;
#pragma unroll
            for (int j = 0; j < 32; ++j) bReg[j] = src[(size_t)j * ldb];
        }
    };

    auto storeT = [&](int st) {
        __nv_bfloat16* Ah = sm + st * STG_ELEMS;
        __nv_bfloat16* Am = Ah + 4608;
        __nv_bfloat16* Bh = Ah + 9216;
        __nv_bfloat16* Bm = Ah + 18432;
        if (!TRA) {
#pragma unroll
            for (int it = 0; it < 4; ++it) {
                int idx = tid + it * 256;
                int r = idx >> 4, q = (idx & 15) << 2;
                uint32_t hp[2], mp[2];
#pragma unroll
                for (int w = 0; w < 2; ++w) {
                    __nv_bfloat16 h0, h1, mq0, mq1;
                    split2(aReg[it * 4 + 2 * w], h0, mq0);
                    split2(aReg[it * 4 + 2 * w + 1], h1, mq1);
                    hp[w] = (uint32_t)__bfloat16_as_ushort(h0) |
                            ((uint32_t)__bfloat16_as_ushort(h1) << 16);
                    mp[w] = (uint32_t)__bfloat16_as_ushort(mq0) |
                            ((uint32_t)__bfloat16_as_ushort(mq1) << 16);
                }
                *(uint2*)(Ah + r * SMS + q) = make_uint2(hp[0], hp[1]);
                *(uint2*)(Am + r * SMS + q) = make_uint2(mp[0], mp[1]);
            }
        } else {
            const int r = tid & 63, cb = (tid >> 6) << 4;
#pragma unroll
            for (int j = 0; j < 16; ++j) {
                __nv_bfloat16 h, m;
                split2(aReg[j], h, m);
                Ah[r * SMS + cb + j] = h;
                Am[r * SMS + cb + j] = m;
            }
        }
        if (!TRB) {
#pragma unroll
            for (int it = 0; it < 8; ++it) {
                int idx = tid + it * 256;
                int r = idx >> 4, q = (idx & 15) << 2;
                uint32_t hp[2], mp[2];
#pragma unroll
                for (int w = 0; w < 2; ++w) {
                    __nv_bfloat16 h0, h1, mq0, mq1;
                    split2(bReg[it * 4 + 2 * w], h0, mq0);
                    split2(bReg[it * 4 + 2 * w + 1], h1, mq1);
                    hp[w] = (uint32_t)__bfloat16_as_ushort(h0) |
                            ((uint32_t)__bfloat16_as_ushort(h1) << 16);
                    mp[w] = (uint32_t)__bfloat16_as_ushort(mq0) |
                            ((uint32_t)__bfloat16_as_ushort(mq1) << 16);
                }
                *(uint2*)(Bh + r * SMS + q) = make_uint2(hp[0], hp[1]);
                *(uint2*)(Bm + r * SMS + q) = make_uint2(mp[0], mp[1]);
            }
        } else {
            const int r = tid & 127, cb = (tid >> 7) << 5;
#pragma unroll
            for (int j = 0; j < 32; ++j) {
                __nv_bfloat16 h, m;
                split2(bReg[j], h, m);
                Bh[r * SMS + cb + j] = h;
                Bm[r * SMS + cb + j] = m;
            }
        }
    };

    auto compute = [&](int st) {
        const __nv_bfloat16* base = sm + st * STG_ELEMS;
#pragma unroll
        for (int p = 0; p < 3; ++p) {
            const __nv_bfloat16* As = base + (p == 2 ? 4608 : 0);
            const __nv_bfloat16* Bs = base + (p == 1 ? 18432 : 9216);
#pragma unroll
            for (int kk = 0; kk < 4; ++kk) {
                uint32_t af[2][4], bf[4][2];
#pragma unroll
                for (int mt = 0; mt < 2; ++mt) {
                    const __nv_bfloat16* p0 =
                        As + (wy * 32 + mt * 16 + g) * SMS + kk * 16 + 2 * tg;
                    const __nv_bfloat16* p1 = p0 + 8 * SMS;
                    af[mt][0] = *(const uint32_t*)p0;
                    af[mt][1] = *(const uint32_t*)p1;
                    af[mt][2] = *(const uint32_t*)(p0 + 8);
                    af[mt][3] = *(const uint32_t*)(p1 + 8);
                }
#pragma unroll
                for (int nt = 0; nt < 4; ++nt) {
                    const __nv_bfloat16* p0 =
                        Bs + (wx * 32 + nt * 8 + g) * SMS + kk * 16 + 2 * tg;
                    bf[nt][0] = *(const uint32_t*)p0;
                    bf[nt][1] = *(const uint32_t*)(p0 + 8);
                }
#pragma unroll
                for (int mt = 0; mt < 2; ++mt)
#pragma unroll
                    for (int nt = 0; nt < 4; ++nt)
                        mma16816(acc[mt][nt], af[mt][0], af[mt][1], af[mt][2], af[mt][3],
                                 bf[nt][0], bf[nt][1]);
            }
        }
    };

    loadT(0);
    storeT(0);
    __syncthreads();
    for (int t = 0; t < T; ++t) {
        if (t + 1 < T) loadT(t + 1);
        compute(t & 1);
        if (t + 1 < T) storeT((t + 1) & 1);
        __syncthreads();
    }

    // ---- epilogue ----
#pragma unroll
    for (int mt = 0; mt < 2; ++mt) {
#pragma unroll
        for (int nt = 0; nt < 4; ++nt) {
#pragma unroll
            for (int half = 0; half < 2; ++half) {
                int r = m0 + wy * 32 + mt * 16 + g + half * 8;
                int c = n0 + wx * 32 + nt * 8 + 2 * tg;
                float v0 = alpha * acc[mt][nt][half * 2 + 0];
                float v1 = alpha * acc[mt][nt][half * 2 + 1];
                if (bias) { v0 += bias[c]; v1 += bias[c + 1]; }
                if (beta != 0.0f) {
                    v0 += beta * C[(size_t)r * ldc + c];
                    v1 += beta * C[(size_t)r * ldc + c + 1];
                }
                if (diagAdd != 0.0f) {
                    if (r == c) v0 += diagAdd;
                    if (r == c + 1) v1 += diagAdd;
                }
                if (flags & 1) { v0 = fmaxf(v0, 0.0f); v1 = fmaxf(v1, 0.0f); }
                *(float2*)(C + (size_t)r * ldc + c) = make_float2(v0, v1);
            }
        }
    }
}

// ================= fast potrf (128x128 diag block) + diag-block inverse =================
// Panel-blocked (32-col panels) factorization; Dinv built afterwards via per-warp
// 32x32 triangular inversion + two levels of block bisection. All fp32 in smem.
extern __shared__ float s_potrf[];
__global__ __launch_bounds__(256) void potrf_diag_kernel(float* A, int lda, int k,
                                                         float* Dinv) {
    float* sL = s_potrf;                // [128*129]
    float* sX = s_potrf + 128 * 129;    // [128*129]
    float* sc = sX + 128 * 129;         // [64*64] scratch
    const int tid = threadIdx.x;
    float* Ab = A + (size_t)k * NB * lda + (size_t)k * NB;

    for (int idx = tid; idx < NB * NB; idx += 256) {
        int r = idx >> 7, c = idx & 127;
        sL[r * 129 + c] = Ab[(size_t)r * lda + c];
    }
    for (int idx = tid; idx < 128 * 129; idx += 256) sX[idx] = 0.0f;
    __syncthreads();

    // ---- blocked factorization, 32-wide panels ----
    for (int p = 0; p < 4; ++p) {
        const int pj = p * 32, pe = pj + 32;
        for (int j = pj; j < pe; ++j) {
            if (tid == 0) sL[j * 129 + j] = sqrtf(sL[j * 129 + j]);
            __syncthreads();
            float invd = 1.0f / sL[j * 129 + j];
            for (int i = j + 1 + tid; i < 128; i += 256) sL[i * 129 + j] *= invd;
            __syncthreads();
            // in-panel trailing: cols j+1..pe-1, rows c..127
            const int tx = tid & 7, ty = tid >> 3;
            for (int c = j + 1 + tx; c < pe; c += 8) {
                float lcj = sL[c * 129 + j];
                for (int i = c + ty; i < 128; i += 32)
                    sL[i * 129 + c] -= sL[i * 129 + j] * lcj;
            }
            __syncthreads();
        }
        // rank-32 trailing update for cols pe..127 (lower tiles only)
        if (pe < 128) {
            const int i = tid & 127;
            if (i >= pe) {
                float a[32];
#pragma unroll
                for (int kk = 0; kk < 32; ++kk) a[kk] = sL[i * 129 + pj + kk];
                for (int c = pe + (tid >> 7); c <= i; c += 2) {
                    float s = 0.0f;
#pragma unroll
                    for (int kk = 0; kk < 32; ++kk) s += a[kk] * sL[c * 129 + pj + kk];
                    sL[i * 129 + c] -= s;
                }
            }
            __syncthreads();
        }
    }

    // ---- Dinv = inv(L): 4 warp-local 32x32 inversions ----
    {
        const int w = tid >> 5, lane = tid & 31;
        if (w < 4) {
            const int b = w * 32, c = lane;
            float x[32];
#pragma unroll
            for (int r = 0; r < 32; ++r) x[r] = 0.0f;
#pragma unroll
            for (int r = 0; r < 32; ++r) {
                if (r >= c) {
                    float s = (r == c) ? 1.0f : 0.0f;
#pragma unroll
                    for (int kk = 0; kk < 32; ++kk)
                        if (kk >= c && kk < r) s -= sL[(b + r) * 129 + b + kk] * x[kk];
                    x[r] = s / sL[(b + r) * 129 + b + r];
                }
            }
#pragma unroll
            for (int r = 0; r < 32; ++r) sX[(b + r) * 129 + b + c] = x[r];
        }
    }
    __syncthreads();
    // ---- combine 32 -> 64 (two pairs): X21 = -X22 * L21 * X11 ----
    {
        const int p2 = tid >> 7, t = tid & 127;
        const int b = p2 * 64;
        float* tmp = sc + p2 * 1024;
#pragma unroll
        for (int q = 0; q < 8; ++q) {
            int idx = t + q * 128;
            int r = idx >> 5, c = idx & 31;
            float s = 0.0f;
#pragma unroll
            for (int kk = 0; kk < 32; ++kk)
                s += sL[(b + 32 + r) * 129 + b + kk] * sX[(b + kk) * 129 + b + c];
            tmp[r * 32 + c] = s;
        }
        __syncthreads();
#pragma unroll
        for (int q = 0; q < 8; ++q) {
            int idx = t + q * 128;
            int r = idx >> 5, c = idx & 31;
            float s = 0.0f;
#pragma unroll
            for (int kk = 0; kk < 32; ++kk)
                s += sX[(b + 32 + r) * 129 + b + 32 + kk] * tmp[kk * 32 + c];
            sX[(b + 32 + r) * 129 + b + c] = -s;
        }
    }
    __syncthreads();
    // ---- combine 64 -> 128: X21 = -X22 * L21 * X11 ----
    {
#pragma unroll
        for (int q = 0; q < 16; ++q) {
            int idx = tid + q * 256;
            int r = idx >> 6, c = idx & 63;
            float s = 0.0f;
            for (int kk = 0; kk < 64; ++kk)
                s += sL[(64 + r) * 129 + kk] * sX[kk * 129 + c];
            sc[r * 64 + c] = s;
        }
        __syncthreads();
#pragma unroll
        for (int q = 0; q < 16; ++q) {
            int idx = tid + q * 256;
            int r = idx >> 6, c = idx & 63;
            float s = 0.0f;
            for (int kk = 0; kk < 64; ++kk)
                s += sX[(64 + r) * 129 + 64 + kk] * sc[kk * 64 + c];
            sX[(64 + r) * 129 + c] = -s;
        }
    }
    __syncthreads();
    // ---- write out: L (lower, zero upper) and Dinv ----
    for (int idx = tid; idx < NB * NB; idx += 256) {
        int r = idx >> 7, c = idx & 127;
        Ab[(size_t)r * lda + c] = (c <= r) ? sL[r * 129 + c] : 0.0f;
        Dinv[idx] = sX[r * 129 + c];
    }
}

// ================= small utility kernels =================
__global__ void place_dinv_kernel(float* __restrict__ Linv, const float* __restrict__ Dinv) {
    for (int idx = blockIdx.x * blockDim.x + threadIdx.x; idx < 8 * NB * NB;
         idx += gridDim.x * blockDim.x) {
        int k = idx >> 14;
        int rem = idx & (NB * NB - 1);
        int r = rem >> 7, c = rem & (NB - 1);
        Linv[(long long)(k * NB + r) * Nn + k * NB + c] = Dinv[idx];
    }
}

__global__ void transpose_kernel(const float* __restrict__ src, float* __restrict__ dst) {
    __shared__ float t[32][33];
    int bx = blockIdx.x * 32, by = blockIdx.y * 32;
    t[threadIdx.y][threadIdx.x] = src[(size_t)(by + threadIdx.y) * Nn + bx + threadIdx.x];
    __syncthreads();
    dst[(size_t)(bx + threadIdx.y) * Nn + by + threadIdx.x] = t[threadIdx.x][threadIdx.y];
}

// ================= host orchestration =================
template <int TRA, int TRB>
static void gm(const float* A, int lda, long long sA, const float* B, int ldb, long long sB,
               int K, float* C, int ldc, long long sC, int M, int N, const float* bias,
               float alpha, float beta, float dAdd, int flags, int batch) {
    gemm_mma<TRA, TRB><<<dim3(N / 128, M / 64, batch), 256, MMA_SMEM>>>(
        A, lda, sA, B, ldb, sB, K, C, ldc, sC, bias, alpha, beta, dAdd, flags);
}

static const int POTRF_SMEM = (2 * 128 * 129 + 64 * 64) * (int)sizeof(float);  // 148480

static void chol_inplace(float* A, float* Dinv) {
    for (int k = 0; k < Nn / NB; ++k) {
        potrf_diag_kernel<<<1, 256, POTRF_SMEM>>>(A, Nn, k, Dinv + (size_t)k * NB * NB);
        int rem = Nn - (k + 1) * NB;
        if (rem > 0) {
            float* panel = A + (size_t)(k + 1) * NB * Nn + (size_t)k * NB;
            // panel := panel * Dinv^T (in place; blocks read their rows before writing)
            gm<0, 0>(panel, Nn, 0, Dinv + (size_t)k * NB * NB, NB, 0, NB, panel, Nn, 0,
                     rem, NB, nullptr, 1.0f, 0.0f, 0.0f, 0, 1);
            // trailing syrk (lower tiles only): At -= panel * panel^T
            float* At = A + (size_t)(k + 1) * NB * Nn + (size_t)(k + 1) * NB;
            gm<0, 0>(panel, Nn, 0, panel, Nn, 0, NB, At, Nn, 0, rem, rem, nullptr, -1.0f,
                     1.0f, 0.0f, 2, 1);
        }
    }
}

static void build_linv(const float* A, float* Linv, const float* Dinv, float* tmp) {
    cudaMemsetAsync(Linv, 0, (size_t)Nn * Nn * sizeof(float));
    place_dinv_kernel<<<128, 256>>>(Linv, Dinv);
    for (int s = 128; s <= 512; s <<= 1) {
        int P = Nn / (2 * s);
        long long str = 2LL * s * (Nn + 1);
        gm<0, 1>(A + (long long)s * Nn, Nn, str, Linv, Nn, str, s, tmp, s, (long long)s * s,
                 s, s, nullptr, 1.0f, 0.0f, 0.0f, 0, P);
        gm<0, 1>(Linv + (long long)s * (Nn + 1), Nn, str, tmp, s, (long long)s * s, s,
                 Linv + (long long)s * Nn, Nn, str, s, s, nullptr, -1.0f, 0.0f, 0.0f, 0, P);
    }
}

extern "C" void kernel_launch(void* const* d_in, const int* in_sizes, int n_in, void* d_out,
                              int out_size) {
    const float* x = (const float*)d_in[0];
    const float* Va = (const float*)d_in[1];
    const float* ba = (const float*)d_in[2];
    const float* Vin = (const float*)d_in[3];
    const float* bin = (const float*)d_in[4];
    const float* Vb = (const float*)d_in[5];
    float* out = (float*)d_out;

    float *dA, *dLinv, *dDinv, *dTmp, *dW, *dT, *dGamma, *dS, *dAw, *dCur, *dCur2;
    cudaGetSymbolAddress((void**)&dA, g_A);
    cudaGetSymbolAddress((void**)&dLinv, g_Linv);
    cudaGetSymbolAddress((void**)&dDinv, g_Dinv);
    cudaGetSymbolAddress((void**)&dTmp, g_tmp);
    cudaGetSymbolAddress((void**)&dW, g_W);
    cudaGetSymbolAddress((void**)&dT, g_T);
    cudaGetSymbolAddress((void**)&dGamma, g_gamma);
    cudaGetSymbolAddress((void**)&dS, g_S);
    cudaGetSymbolAddress((void**)&dAw, g_aw);
    cudaGetSymbolAddress((void**)&dCur, g_cur);
    cudaGetSymbolAddress((void**)&dCur2, g_cur2);
    cudaFuncSetAttribute(potrf_diag_kernel, cudaFuncAttributeMaxDynamicSharedMemorySize,
                         POTRF_SMEM);
    cudaFuncSetAttribute(gemm_mma<0, 0>, cudaFuncAttributeMaxDynamicSharedMemorySize,
                         MMA_SMEM);
    cudaFuncSetAttribute(gemm_mma<0, 1>, cudaFuncAttributeMaxDynamicSharedMemorySize,
                         MMA_SMEM);
    cudaFuncSetAttribute(gemm_mma<1, 1>, cudaFuncAttributeMaxDynamicSharedMemorySize,
                         MMA_SMEM);

    // ---- Layer A: M = I + Va^T Va ; factor ; Linv ; a_weight = Va Linv^T ----
    gm<1, 1>(Va, Nn, 0, Va, Nn, 0, Nn, dA, Nn, 0, Nn, Nn, nullptr, 1.0f, 0.0f, 1.0f, 2, 1);
    chol_inplace(dA, dDinv);
    build_linv(dA, dLinv, dDinv, dTmp);
    gm<0, 0>(Va, Nn, 0, dLinv, Nn, 0, Nn, dAw, Nn, 0, Nn, Nn, nullptr, 1.0f, 0.0f, 0.0f, 0, 1);

    // first = x @ a_weight^T + ba -> out
    gm<0, 0>(x, Nn, 0, dAw, Nn, 0, Nn, out, Nn, 0, BATCH, Nn, ba, 1.0f, 0.0f, 0.0f, 0, 1);
    cudaMemcpyAsync(dCur, x, (size_t)BATCH * Nn * sizeof(float), cudaMemcpyDeviceToDevice);

    float* cur = dCur;
    float* cur2 = dCur2;
    for (int i = 0; i < NL; ++i) {
        // T = gamma @ Linv^T  (layer 0: gamma = I -> T = Linv^T)
        if (i == 0)
            transpose_kernel<<<dim3(32, 32), dim3(32, 32)>>>(dLinv, dT);
        else
            gm<0, 0>(dGamma, Nn, 0, dLinv, Nn, 0, Nn, dT, Nn, 0, Nn, Nn, nullptr, 1.0f,
                     0.0f, 0.0f, 0, 1);
        // W = V_i @ Linv^T
        gm<0, 0>(Vin + (size_t)i * Nn * Nn, Nn, 0, dLinv, Nn, 0, Nn, dW, Nn, 0, Nn, Nn,
                 nullptr, 1.0f, 0.0f, 0.0f, 0, 1);
        // cur = relu(cur @ W^T + b_i)
        gm<0, 0>(cur, Nn, 0, dW, Nn, 0, Nn, cur2, Nn, 0, BATCH, Nn, bin + (size_t)i * Nn,
                 1.0f, 0.0f, 0.0f, 1, 1);
        { float* t = cur; cur = cur2; cur2 = t; }
        // S += T T^T (full symmetric accumulator; replaces per-layer sigma choleskys)
        gm<0, 0>(dT, Nn, 0, dT, Nn, 0, Nn, dS, Nn, 0, Nn, Nn, nullptr, 1.0f,
                 (i == 0) ? 0.0f : 1.0f, 0.0f, 0, 1);
        // gamma = T @ W^T
        gm<0, 0>(dT, Nn, 0, dW, Nn, 0, Nn, dGamma, Nn, 0, Nn, Nn, nullptr, 1.0f, 0.0f,
                 0.0f, 0, 1);
        // M = I + 0.5 W W^T ; factor ; Linv
        gm<0, 0>(dW, Nn, 0, dW, Nn, 0, Nn, dA, Nn, 0, Nn, Nn, nullptr, 0.5f, 0.0f, 1.0f, 2, 1);
        chol_inplace(dA, dDinv);
        build_linv(dA, dLinv, dDinv, dTmp);
    }

    // ---- Final layer B ----
    // Wb = Vb @ Linv^T -> dGamma (gamma dead here)
    gm<0, 0>(Vb, Nn, 0, dLinv, Nn, 0, Nn, dGamma, Nn, 0, Nn, Nn, nullptr, 1.0f, 0.0f, 0.0f, 0, 1);
    // U = aw @ S -> dT  (S full symmetric)
    gm<0, 0>(dAw, Nn, 0, dS, Nn, 0, Nn, dT, Nn, 0, Nn, Nn, nullptr, 1.0f, 0.0f, 0.0f, 0, 1);
    // M = I + U aw^T (= I + aw S aw^T) ; factor ; Linv_sigma
    gm<0, 0>(dT, Nn, 0, dAw, Nn, 0, Nn, dA, Nn, 0, Nn, Nn, nullptr, 1.0f, 0.0f, 1.0f, 2, 1);
    chol_inplace(dA, dDinv);
    build_linv(dA, dLinv, dDinv, dTmp);
    // b_weight = Linv_sigma^T @ Wb -> dW
    gm<1, 1>(dLinv, Nn, 0, dGamma, Nn, 0, Nn, dW, Nn, 0, Nn, Nn, nullptr, 1.0f, 0.0f, 0.0f, 0, 1);
    // out += cur @ b_weight^T
    gm<0, 0>(cur, Nn, 0, dW, Nn, 0, Nn, out, Nn, 0, BATCH, Nn, nullptr, 1.0f, 1.0f, 0.0f, 0, 1);
}